// round 17
// baseline (speedup 1.0000x reference)
#include <cuda_runtime.h>
#include <limits.h>
#include <stdint.h>

typedef unsigned long long u64;

// Problem constants
#define BATCH 32
#define NPTS  131072            // 2^17
#define BN    (BATCH*NPTS)      // 4194304
#define TSEL  32768
#define CELL  0.05f

// Batch-partitioned hash: batch b owns slots [b<<18, (b+1)<<18)
// Entries are COMPLEMENT-encoded: entry = ~((key<<32)|minIdx); EMPTY = 0
#define LBITS 18
#define LMASK ((1u<<LBITS)-1)
#define HSIZE (BATCH<<LBITS)     // 2^23 total slots, 64MB

// Mega config: 2048 blocks x 2048 points (256 thr x 8 rounds)
#define NBLK  2048
#define CHUNK 2048
#define SCANT 256
#define ROUNDS 8
#define BPB   (NPTS/CHUNK)       // 64 blocks per batch

// Tail tiling
#define TNB    1024
#define TCHUNK 4096
#define TITEMS 16
#define TAILBLK (TNB + BATCH + 64)

// Lookback state flags
#define FLAG1 (1ull << 62)       // aggregate available
#define FLAG2 (2ull << 62)       // inclusive available
#define SFMASK (3ull << 62)
#define PUBBIT (1ull << 63)
#define VALMASK 0x3FFFFFFFull

// Output layout (flattened, concatenated, all f32)
#define OFF_Y    0
#define OFF_IDX  (BATCH*TSEL*3)
#define OFF_MASK (OFF_IDX + BATCH*TSEL*2)
#define OFF_UL   (OFF_MASK + BATCH*TSEL)
#define OFF_ULI  (OFF_UL + BN)

// Scratch (static zero-init == EMPTY / cleared state for first replay)
__device__ u64 d_h[HSIZE];
__device__ unsigned d_slot[BN];        // after mega: fi per point
__device__ u64 d_state[NBLK];
__device__ u64 d_bbase[BATCH+1];       // PUBBIT protocol (cleared in tail)
__device__ unsigned d_bbase2[BATCH+1]; // plain snapshot for tail (no clear needed)
__device__ unsigned d_bdone[BATCH];
__device__ unsigned d_ticket;

__device__ __forceinline__ int quant(float v) {
    return (int)rintf(__fdiv_rn(v, CELL));
}
__device__ __forceinline__ unsigned mkkey(int b, int q0, int q1, int q2) {
    return ((unsigned)b << 27) | ((unsigned)(q0 + 256) << 18)
         | ((unsigned)(q1 + 256) << 9) | (unsigned)(q2 + 256);
}
__device__ __forceinline__ unsigned khash18(unsigned k) {
    return (k * 2654435761u) >> (32 - LBITS);
}

// ---------------------------------------------------------------------------
// K1: MEGA — per-block insert (coalesced rounds) + per-batch barrier +
//     flags (ballot scan) + warp-parallel decoupled lookback + scatters.
//     Safe vs R7: this kernel NEVER writes d_h after the barrier.
__global__ void __launch_bounds__(SCANT) k_mega(const float* __restrict__ x,
                                                float* __restrict__ out) {
    __shared__ int s_tb;
    __shared__ int s_ws[8];
    __shared__ unsigned s_excl, s_pb;

    int t = threadIdx.x;
    if (t == 0) s_tb = (int)atomicAdd(&d_ticket, 1u);
    __syncthreads();
    int tb = s_tb;
    int i0 = tb * CHUNK;
    int b  = i0 >> 17;
    unsigned base = (unsigned)b << LBITS;
    int lane = t & 31, wid = t >> 5;

    // ---- Phase A: insert own chunk, coalesced 1pt/thread rounds ----
    unsigned hh[ROUNDS];
    #pragma unroll
    for (int e = 0; e < ROUNDS; e++) {
        int i = i0 + e * SCANT + t;
        float x0 = __ldcs(&x[3*i+0]);
        float x1 = __ldcs(&x[3*i+1]);
        float x2 = __ldcs(&x[3*i+2]);
        unsigned key = mkkey(b, quant(x0), quant(x1), quant(x2));
        u64 enc = ~(((u64)key << 32) | (unsigned)i);
        unsigned hl = khash18(key);
        unsigned h;
        while (true) {
            h = base | hl;
            u64 old = atomicCAS(&d_h[h], 0ull, enc);
            if (old == 0ull) break;
            u64 dec = ~old;
            if ((unsigned)(dec >> 32) == key) {
                if ((unsigned)dec > (unsigned)i)
                    atomicMax(&d_h[h], enc);     // min idx == max encoded
                break;
            }
            hl = (hl + 1) & LMASK;
        }
        hh[e] = h;
    }
    __threadfence();                             // release inserts
    __syncthreads();
    if (t == 0) {
        atomicAdd(&d_bdone[b], 1u);
        while (*(volatile unsigned*)&d_bdone[b] < BPB) __nanosleep(64);
        __threadfence();                         // acquire
    }
    __syncthreads();

    // ---- Phase B: flags + block-local ranks (ballot scan per round) ----
    unsigned hk[ROUNDS];
    int pre[ROUNDS];
    unsigned fmask = 0;
    int runtot = 0;
    #pragma unroll
    for (int e = 0; e < ROUNDS; e++) {
        int i = i0 + e * SCANT + t;
        u64 dec = ~__ldcg(&d_h[hh[e]]);
        unsigned fiv = (unsigned)dec;
        hk[e] = (unsigned)(dec >> 32);
        __stcs(&d_slot[i], fiv);                 // fi for tail (firsts: fi==i)
        unsigned f = (fiv == (unsigned)i);
        fmask |= f << e;
        unsigned bal = __ballot_sync(0xFFFFFFFFu, f != 0);
        if (lane == 0) s_ws[wid] = __popc(bal);
        int wpre = __popc(bal & ((1u << lane) - 1u));
        __syncthreads();
        int woff = 0, tot = 0;
        #pragma unroll
        for (int k = 0; k < 8; k++) {
            int v = s_ws[k];
            tot += v;
            if (k < wid) woff += v;
        }
        pre[e] = runtot + woff + wpre;           // block-local exclusive rank
        runtot += tot;
        __syncthreads();
    }
    int agg = runtot;

    // ---- warp-parallel decoupled lookback (warp 0) ----
    if (t < 32) {
        unsigned excl = 0;
        if (tb == 0) {
            if (t == 0) {
                __threadfence();
                atomicExch(&d_state[0], FLAG2 | (u64)agg);
            }
        } else {
            if (t == 0) atomicExch(&d_state[tb], FLAG1 | (u64)agg);
            int wbase = tb;
            while (true) {
                int j = wbase - 32 + t;
                u64 s;
                if (j >= 0) {
                    s = *(volatile u64*)&d_state[j];
                    while ((s & SFMASK) == 0)
                        s = *(volatile u64*)&d_state[j];
                } else {
                    s = FLAG2;
                }
                unsigned incm = __ballot_sync(0xFFFFFFFFu, (s & SFMASK) == FLAG2);
                if (incm) {
                    int hi = 31 - __clz(incm);
                    unsigned contrib = (t >= hi) ? (unsigned)(s & VALMASK) : 0u;
                    #pragma unroll
                    for (int o = 16; o; o >>= 1)
                        contrib += __shfl_xor_sync(0xFFFFFFFFu, contrib, o);
                    excl += contrib;
                    break;
                } else {
                    unsigned contrib = (unsigned)(s & VALMASK);
                    #pragma unroll
                    for (int o = 16; o; o >>= 1)
                        contrib += __shfl_xor_sync(0xFFFFFFFFu, contrib, o);
                    excl += contrib;
                    wbase -= 32;
                }
            }
            if (t == 0) {
                __threadfence();
                atomicExch(&d_state[tb], FLAG2 | (u64)(excl + (unsigned)agg));
            }
        }
        if (t == 0) {
            int m = tb / BPB;
            unsigned pbv;
            if (tb % BPB == 0) {
                d_bbase2[m] = excl;              // snapshot for tail
                __threadfence();
                atomicExch(&d_bbase[m], PUBBIT | (u64)excl);
                pbv = excl;
            } else {
                while (true) {
                    u64 s = *(volatile u64*)&d_bbase[m];
                    if (s & PUBBIT) { pbv = (unsigned)(s & VALMASK); break; }
                }
            }
            if (tb == NBLK - 1) {
                d_bbase2[BATCH] = excl + (unsigned)agg;
                __threadfence();
            }
            s_excl = excl;
            s_pb = pbv;
        }
    }
    __syncthreads();

    int pb = (int)s_pb;
    int excl = (int)s_excl;

    // ---- scatter: firsts — UL, ULI, selected y/idx/mask (y from key) ----
    #pragma unroll
    for (int e = 0; e < ROUNDS; e++) {
        if ((fmask >> e) & 1) {
            int i = i0 + e * SCANT + t;
            int p = excl + pre[e];
            out[OFF_UL + i] = (float)p;
            __stcs(&out[OFF_ULI + p], (float)i);
            int r = p - pb;
            if (r < TSEL) {
                unsigned key = hk[e];
                int il = i & (NPTS - 1);
                float y0 = CELL * (float)((int)((key >> 18) & 511) - 256);
                float y1 = CELL * (float)((int)((key >> 9) & 511) - 256);
                float y2 = CELL * (float)((int)(key & 511) - 256);
                int o = b * TSEL + r;
                __stcs(&out[OFF_Y + 3*o + 0], y0);
                __stcs(&out[OFF_Y + 3*o + 1], y1);
                __stcs(&out[OFF_Y + 3*o + 2], y2);
                __stcs(&out[OFF_IDX + 2*o + 0], (float)b);
                __stcs(&out[OFF_IDX + 2*o + 1], (float)il);
                __stcs(&out[OFF_MASK + o], 1.0f);
            }
        }
    }
}

// ---------------------------------------------------------------------------
// K2: combined tail — UL gather + fixup + SENT tail, then pre-clear of
//     d_h / d_state / d_bdone / d_bbase / d_ticket for the next replay.
//     (readers here use d_bbase2, which is never cleared — only rewritten)
__global__ void k_tail(const float* __restrict__ x, float* __restrict__ out) {
    int blk = blockIdx.x;
    int t = threadIdx.x;

    if (blk < TNB) {
        // ul_idx for ALL points, branch-free: UL[i] = UL[fi]
        int i0 = blk * TCHUNK + t * TITEMS;
        unsigned f[TITEMS];
        #pragma unroll
        for (int v = 0; v < 4; v++) {
            uint4 f4 = *(const uint4*)(d_slot + i0 + 4*v);
            f[4*v+0] = f4.x; f[4*v+1] = f4.y; f[4*v+2] = f4.z; f[4*v+3] = f4.w;
        }
        float r[TITEMS];
        #pragma unroll
        for (int e = 0; e < TITEMS; e++)
            r[e] = __ldcg(&out[OFF_UL + f[e]]);
        #pragma unroll
        for (int v = 0; v < 4; v++) {
            float4 r4 = make_float4(r[4*v+0], r[4*v+1], r[4*v+2], r[4*v+3]);
            __stcs((float4*)(out + OFF_UL + i0 + 4*v), r4);
        }
    } else {
        int fb = blk - TNB;
        if (fb >= BATCH) {
            // ULI SENT tail
            int U = (int)d_bbase2[BATCH];
            int nb = 64;
            for (int i = U + (fb - BATCH) * blockDim.x + t; i < BN; i += nb * blockDim.x)
                __stcs(&out[OFF_ULI + i], (float)BN);
        } else {
            int pb0 = (int)d_bbase2[fb];
            int pb1 = (int)d_bbase2[fb + 1];
            int Kb = pb1 - pb0;
            if (Kb < TSEL) {
                // Dormant slow path (d_slot holds fi: first <=> fi == i)
                __shared__ int s_run;
                __shared__ int cw[8];
                if (t == 0) s_run = 0;
                __syncthreads();
                for (int base = 0; base < NPTS; base += SCANT) {
                    int il = base + t;
                    int i = fb * NPTS + il;
                    int isf = (d_slot[i] == (unsigned)i);
                    int lane = t & 31, wid = t >> 5;
                    int incv = isf;
                    #pragma unroll
                    for (int o = 1; o < 32; o <<= 1) {
                        int u = __shfl_up_sync(0xFFFFFFFFu, incv, o);
                        if (lane >= o) incv += u;
                    }
                    if (lane == 31) cw[wid] = incv;
                    __syncthreads();
                    int woff = 0;
                    for (int k = 0; k < wid; k++) woff += cw[k];
                    int r = s_run + woff + incv - isf;
                    if (!isf) {
                        int tt = Kb + (il - r);
                        if (tt < TSEL) {
                            float y0 = CELL * rintf(__fdiv_rn(__ldg(&x[3*i+0]), CELL));
                            float y1 = CELL * rintf(__fdiv_rn(__ldg(&x[3*i+1]), CELL));
                            float y2 = CELL * rintf(__fdiv_rn(__ldg(&x[3*i+2]), CELL));
                            int o = fb * TSEL + tt;
                            out[OFF_Y + 3*o + 0] = y0;
                            out[OFF_Y + 3*o + 1] = y1;
                            out[OFF_Y + 3*o + 2] = y2;
                            out[OFF_IDX + 2*o + 0] = (float)fb;
                            out[OFF_IDX + 2*o + 1] = (float)il;
                            out[OFF_MASK + o] = 0.0f;
                        }
                    }
                    __syncthreads();
                    if (t == 0) {
                        int tot = 0;
                        #pragma unroll
                        for (int k = 0; k < 8; k++) tot += cw[k];
                        s_run += tot;
                    }
                    __syncthreads();
                }
            }
        }
    }

    // pre-clear for next replay (no tail block reads these)
    {
        unsigned gid = (unsigned)blk * SCANT + t;
        unsigned stride = (unsigned)TAILBLK * SCANT;
        ulonglong2* p = (ulonglong2*)d_h;
        const unsigned n = HSIZE / 2;
        for (unsigned j = gid; j < n; j += stride)
            __stcs(&p[j], make_ulonglong2(0ull, 0ull));
        for (unsigned j = gid; j < NBLK; j += stride)
            d_state[j] = 0;
        if (gid < BATCH) d_bdone[gid] = 0;
        if (gid <= BATCH) d_bbase[gid] = 0;
        if (gid == 0) d_ticket = 0;
    }
}

// ---------------------------------------------------------------------------
extern "C" void kernel_launch(void* const* d_in, const int* in_sizes, int n_in,
                              void* d_out, int out_size) {
    const float* x = (const float*)d_in[0];
    float* out = (float*)d_out;
    (void)in_sizes; (void)n_in; (void)out_size;

    k_mega<<<NBLK, SCANT>>>(x, out);
    k_tail<<<TAILBLK, SCANT>>>(x, out);
}